// round 5
// baseline (speedup 1.0000x reference)
#include <cuda_runtime.h>

// LDPC BP, (7,4) Hamming, 5 iters, B=262144. Latency-bound -> ILP=2 per thread.
//
// Half-domain: Th=(llr+total)/2, mh=m_new/2, t=tanh(Th-mh), out=4*Th_final.
// rows: r0={0,2,4,6}, r1={1,2,5,6}, r2={3,4,5,6}; deg={1,1,2,1,2,2,3}
// deg-1 vars (v0,v1,v3): edge arg == llr+1 constant for iters>=2.
// iter 1: edge args = llr_v/2, shared per variable.

__device__ __forceinline__ float tanhf32(float x) {
    float y;
    asm("tanh.approx.f32 %0, %1;" : "=f"(y) : "f"(x));
    return y;
}

struct St {
    float l0, l1, l2, l3, l4, l5, l6;
    float c0h, c1h, c3h;            // 0.5*tanh(l+1) for deg-1 edges
    float base2, base4, base5, base6;
    float T2, T4, T5, T6;
    float m01, m02, m03, m11, m12, m13, m21, m22, m23;
    float m00, m10, m20;
};

__device__ __forceinline__ void init_consts(St& s) {
    s.c0h = 0.5f * tanhf32(s.l0 + 1.0f);
    s.c1h = 0.5f * tanhf32(s.l1 + 1.0f);
    s.c3h = 0.5f * tanhf32(s.l3 + 1.0f);
    s.base2 = s.l2 + 0.5f;
    s.base4 = s.l4 + 0.5f;
    s.base5 = s.l5 + 0.5f;
    s.base6 = s.l6;
}

__device__ __forceinline__ void iter1(St& s) {
    float tv0 = tanhf32(0.5f * s.l0);
    float tv1 = tanhf32(0.5f * s.l1);
    float tv2 = tanhf32(0.5f * s.l2);
    float tv3 = tanhf32(0.5f * s.l3);
    float tv4 = tanhf32(0.5f * s.l4);
    float tv5 = tanhf32(0.5f * s.l5);
    float tv6 = tanhf32(0.5f * s.l6);

    float t0h = 0.5f * tv0, t1h = 0.5f * tv1, t3h = 0.5f * tv3;
    float pb0 = tv4 * tv6, pa0 = t0h * tv2;
    s.m01 = t0h * pb0;  s.m02 = pa0 * tv6;  s.m03 = pa0 * tv4;
    float pb1 = tv5 * tv6, pa1 = t1h * tv2;
    s.m11 = t1h * pb1;  s.m12 = pa1 * tv6;  s.m13 = pa1 * tv5;
    float pb2 = tv5 * tv6, pa2 = t3h * tv4;
    s.m21 = t3h * pb2;  s.m22 = pa2 * tv6;  s.m23 = pa2 * tv5;

    s.T2 = s.base2 + (s.m01 + s.m11);
    s.T4 = s.base4 + (s.m02 + s.m21);
    s.T5 = s.base5 + (s.m12 + s.m22);
    s.T6 = s.base6 + ((s.m03 + s.m13) + s.m23);
}

template <bool LAST>
__device__ __forceinline__ void iterN(St& s) {
    float t01 = tanhf32(s.T2 - s.m01), t02 = tanhf32(s.T4 - s.m02), t03 = tanhf32(s.T6 - s.m03);
    float t11 = tanhf32(s.T2 - s.m11), t12 = tanhf32(s.T5 - s.m12), t13 = tanhf32(s.T6 - s.m13);
    float t21 = tanhf32(s.T4 - s.m21), t22 = tanhf32(s.T5 - s.m22), t23 = tanhf32(s.T6 - s.m23);

    float pb0 = t02 * t03, pa0 = s.c0h * t01;
    s.m01 = s.c0h * pb0;  s.m02 = pa0 * t03;  s.m03 = pa0 * t02;
    float pb1 = t12 * t13, pa1 = s.c1h * t11;
    s.m11 = s.c1h * pb1;  s.m12 = pa1 * t13;  s.m13 = pa1 * t12;
    float pb2 = t22 * t23, pa2 = s.c3h * t21;
    s.m21 = s.c3h * pb2;  s.m22 = pa2 * t23;  s.m23 = pa2 * t22;

    if (LAST) {
        s.m00 = t01 * (0.5f * pb0);
        s.m10 = t11 * (0.5f * pb1);
        s.m20 = t21 * (0.5f * pb2);
    }

    s.T2 = s.base2 + (s.m01 + s.m11);
    s.T4 = s.base4 + (s.m02 + s.m21);
    s.T5 = s.base5 + (s.m12 + s.m22);
    s.T6 = s.base6 + ((s.m03 + s.m13) + s.m23);
}

__global__ __launch_bounds__(256)
void ldpc_bp_kernel(const float2* __restrict__ llr2, float2* __restrict__ out2, int Bpair) {
    int i = blockIdx.x * blockDim.x + threadIdx.x;
    if (i >= Bpair) return;

    // two batch elements per thread: 14 contiguous floats = 7 float2
    const float2* p = llr2 + (size_t)i * 7;
    float2 v0 = p[0], v1 = p[1], v2 = p[2], v3 = p[3], v4 = p[4], v5 = p[5], v6 = p[6];

    St a, b;
    a.l0 = v0.x; a.l1 = v0.y; a.l2 = v1.x; a.l3 = v1.y; a.l4 = v2.x; a.l5 = v2.y; a.l6 = v3.x;
    b.l0 = v3.y; b.l1 = v4.x; b.l2 = v4.y; b.l3 = v5.x; b.l4 = v5.y; b.l5 = v6.x; b.l6 = v6.y;

    init_consts(a); init_consts(b);
    iter1(a); iter1(b);
    iterN<false>(a); iterN<false>(b);
    iterN<false>(a); iterN<false>(b);
    iterN<false>(a); iterN<false>(b);
    iterN<true>(a);  iterN<true>(b);

    float oa0 = 4.0f * ((a.l0 + 1.0f) + a.m00);
    float oa1 = 4.0f * ((a.l1 + 1.0f) + a.m10);
    float oa3 = 4.0f * ((a.l3 + 1.0f) + a.m20);
    float ob0 = 4.0f * ((b.l0 + 1.0f) + b.m00);
    float ob1 = 4.0f * ((b.l1 + 1.0f) + b.m10);
    float ob3 = 4.0f * ((b.l3 + 1.0f) + b.m20);

    float2* q = out2 + (size_t)i * 7;
    q[0] = make_float2(oa0, oa1);
    q[1] = make_float2(4.0f * a.T2, oa3);
    q[2] = make_float2(4.0f * a.T4, 4.0f * a.T5);
    q[3] = make_float2(4.0f * a.T6, ob0);
    q[4] = make_float2(ob1, 4.0f * b.T2);
    q[5] = make_float2(ob3, 4.0f * b.T4);
    q[6] = make_float2(4.0f * b.T5, 4.0f * b.T6);
}

extern "C" void kernel_launch(void* const* d_in, const int* in_sizes, int n_in,
                              void* d_out, int out_size) {
    const float2* llr2 = (const float2*)d_in[0];
    float2* out2 = (float2*)d_out;
    int Bpair = in_sizes[0] / 14;  // 131072 threads, 2 elements each

    const int threads = 256;
    int blocks = (Bpair + threads - 1) / threads;
    ldpc_bp_kernel<<<blocks, threads>>>(llr2, out2, Bpair);
}

// round 6
// speedup vs baseline: 1.0340x; 1.0340x over previous
#include <cuda_runtime.h>

// LDPC BP, (7,4) Hamming, 5 iters, B=262144.
// One element/thread (harness caps regs at 32 — ILP>1 spills).
//
// Half-domain: Th=(llr+total)/2, mh=m_new/2, t=tanh(Th-mh), out=4*Th_final.
// rows: r0={0,2,4,6}, r1={1,2,5,6}, r2={3,4,5,6}; deg={1,1,2,1,2,2,3}
// Structural tanh cuts (all f32, 46 MUFU.TANH total):
//  * deg-1 vars (v0,v1,v3): edge arg == llr+1, constant for iters>=2 -> 3 tanh once
//  * iter 1: all edge args = llr_v/2, shared per variable -> 7 tanh
//  * iters 2..5: 9 tanh each

__device__ __forceinline__ float tanhf32(float x) {
    float y;
    asm("tanh.approx.f32 %0, %1;" : "=f"(y) : "f"(x));
    return y;
}

__global__ __launch_bounds__(128)
void ldpc_bp_kernel(const float* __restrict__ llr, float* __restrict__ out, int B) {
    int b = blockIdx.x * blockDim.x + threadIdx.x;
    if (b >= B) return;

    const float* p = llr + (size_t)b * 7;
    float l0 = p[0], l1 = p[1], l2 = p[2], l3 = p[3], l4 = p[4], l5 = p[5], l6 = p[6];

    // deg-1 constants (valid iters >= 2), halved
    float c0h = 0.5f * tanhf32(l0 + 1.0f);
    float c1h = 0.5f * tanhf32(l1 + 1.0f);
    float c3h = 0.5f * tanhf32(l3 + 1.0f);

    const float base2 = l2 + 0.5f;
    const float base4 = l4 + 0.5f;
    const float base5 = l5 + 0.5f;
    const float base6 = l6;

    float T2, T4, T5, T6;
    float m01, m02, m03;   // row0 -> v2,v4,v6 (half messages)
    float m11, m12, m13;   // row1 -> v2,v5,v6
    float m21, m22, m23;   // row2 -> v4,v5,v6

    // ---------- iteration 1: args = l_v/2, shared per variable ----------
    {
        float tv0 = tanhf32(0.5f * l0);
        float tv1 = tanhf32(0.5f * l1);
        float tv2 = tanhf32(0.5f * l2);
        float tv3 = tanhf32(0.5f * l3);
        float tv4 = tanhf32(0.5f * l4);
        float tv5 = tanhf32(0.5f * l5);
        float tv6 = tanhf32(0.5f * l6);

        float t0h = 0.5f * tv0, t1h = 0.5f * tv1, t3h = 0.5f * tv3;
        float pb0 = tv4 * tv6, pa0 = t0h * tv2;
        m01 = t0h * pb0;  m02 = pa0 * tv6;  m03 = pa0 * tv4;
        float pb1 = tv5 * tv6, pa1 = t1h * tv2;
        m11 = t1h * pb1;  m12 = pa1 * tv6;  m13 = pa1 * tv5;
        float pb2 = tv5 * tv6, pa2 = t3h * tv4;
        m21 = t3h * pb2;  m22 = pa2 * tv6;  m23 = pa2 * tv5;

        T2 = base2 + (m01 + m11);
        T4 = base4 + (m02 + m21);
        T5 = base5 + (m12 + m22);
        T6 = base6 + ((m03 + m13) + m23);
    }

    // ---------- iterations 2..4 ----------
#pragma unroll
    for (int it = 0; it < 3; ++it) {
        float t01 = tanhf32(T2 - m01), t02 = tanhf32(T4 - m02), t03 = tanhf32(T6 - m03);
        float t11 = tanhf32(T2 - m11), t12 = tanhf32(T5 - m12), t13 = tanhf32(T6 - m13);
        float t21 = tanhf32(T4 - m21), t22 = tanhf32(T5 - m22), t23 = tanhf32(T6 - m23);

        float pb0 = t02 * t03, pa0 = c0h * t01;
        m01 = c0h * pb0;  m02 = pa0 * t03;  m03 = pa0 * t02;
        float pb1 = t12 * t13, pa1 = c1h * t11;
        m11 = c1h * pb1;  m12 = pa1 * t13;  m13 = pa1 * t12;
        float pb2 = t22 * t23, pa2 = c3h * t21;
        m21 = c3h * pb2;  m22 = pa2 * t23;  m23 = pa2 * t22;

        T2 = base2 + (m01 + m11);
        T4 = base4 + (m02 + m21);
        T5 = base5 + (m12 + m22);
        T6 = base6 + ((m03 + m13) + m23);
    }

    // ---------- iteration 5 (also deg-1 messages for outputs) ----------
    float m00, m10, m20;
    {
        float t01 = tanhf32(T2 - m01), t02 = tanhf32(T4 - m02), t03 = tanhf32(T6 - m03);
        float t11 = tanhf32(T2 - m11), t12 = tanhf32(T5 - m12), t13 = tanhf32(T6 - m13);
        float t21 = tanhf32(T4 - m21), t22 = tanhf32(T5 - m22), t23 = tanhf32(T6 - m23);

        float pb0 = t02 * t03, pa0 = c0h * t01;
        m01 = c0h * pb0;  m02 = pa0 * t03;  m03 = pa0 * t02;
        m00 = t01 * (0.5f * pb0);
        float pb1 = t12 * t13, pa1 = c1h * t11;
        m11 = c1h * pb1;  m12 = pa1 * t13;  m13 = pa1 * t12;
        m10 = t11 * (0.5f * pb1);
        float pb2 = t22 * t23, pa2 = c3h * t21;
        m21 = c3h * pb2;  m22 = pa2 * t23;  m23 = pa2 * t22;
        m20 = t21 * (0.5f * pb2);

        T2 = base2 + (m01 + m11);
        T4 = base4 + (m02 + m21);
        T5 = base5 + (m12 + m22);
        T6 = base6 + ((m03 + m13) + m23);
    }

    float* q = out + (size_t)b * 7;
    q[0] = 4.0f * ((l0 + 1.0f) + m00);
    q[1] = 4.0f * ((l1 + 1.0f) + m10);
    q[2] = 4.0f * T2;
    q[3] = 4.0f * ((l3 + 1.0f) + m20);
    q[4] = 4.0f * T4;
    q[5] = 4.0f * T5;
    q[6] = 4.0f * T6;
}

extern "C" void kernel_launch(void* const* d_in, const int* in_sizes, int n_in,
                              void* d_out, int out_size) {
    const float* llr = (const float*)d_in[0];
    float* out = (float*)d_out;
    int B = in_sizes[0] / 7;  // 262144

    const int threads = 128;
    int blocks = (B + threads - 1) / threads;  // 2048 blocks -> finer SM balance
    ldpc_bp_kernel<<<blocks, threads>>>(llr, out, B);
}

// round 7
// speedup vs baseline: 1.2362x; 1.1956x over previous
#include <cuda_runtime.h>

// LDPC BP, (7,4) Hamming, 5 iters, B=262144.
// R7: R6 math (46 tanh) + block=256 + smem-staged coalesced float4 I/O.
//
// Half-domain: Th=(llr+total)/2, mh=m_new/2, t=tanh(Th-mh), out=4*Th_final.
// rows: r0={0,2,4,6}, r1={1,2,5,6}, r2={3,4,5,6}; deg={1,1,2,1,2,2,3}
//  * deg-1 vars (v0,v1,v3): edge arg == llr+1, constant for iters>=2 -> 3 tanh once
//  * iter 1: all edge args = llr_v/2, shared per variable -> 7 tanh
//  * iters 2..5: 9 tanh each

__device__ __forceinline__ float tanhf32(float x) {
    float y;
    asm("tanh.approx.f32 %0, %1;" : "=f"(y) : "f"(x));
    return y;
}

#define TPB 256
#define FLOATS_PER_BLK (TPB * 7)          // 1792 floats
#define VEC4_PER_BLK   (FLOATS_PER_BLK/4) // 448

__global__ __launch_bounds__(TPB)
void ldpc_bp_kernel(const float4* __restrict__ llr4, float4* __restrict__ out4) {
    __shared__ float s[FLOATS_PER_BLK];
    int tid = threadIdx.x;

    // ---- coalesced bulk load: 448 float4 per block ----
    {
        const float4* src = llr4 + (size_t)blockIdx.x * VEC4_PER_BLK;
        float4* s4 = reinterpret_cast<float4*>(s);
#pragma unroll
        for (int i = tid; i < VEC4_PER_BLK; i += TPB)
            s4[i] = src[i];
    }
    __syncthreads();

    // stride-7 smem read (7 coprime 32 -> conflict-free)
    const float* p = s + tid * 7;
    float l0 = p[0], l1 = p[1], l2 = p[2], l3 = p[3], l4 = p[4], l5 = p[5], l6 = p[6];

    // deg-1 constants (valid iters >= 2), halved
    float c0h = 0.5f * tanhf32(l0 + 1.0f);
    float c1h = 0.5f * tanhf32(l1 + 1.0f);
    float c3h = 0.5f * tanhf32(l3 + 1.0f);

    const float base2 = l2 + 0.5f;
    const float base4 = l4 + 0.5f;
    const float base5 = l5 + 0.5f;
    const float base6 = l6;

    float T2, T4, T5, T6;
    float m01, m02, m03;   // row0 -> v2,v4,v6 (half messages)
    float m11, m12, m13;   // row1 -> v2,v5,v6
    float m21, m22, m23;   // row2 -> v4,v5,v6

    // ---------- iteration 1: args = l_v/2, shared per variable ----------
    {
        float tv0 = tanhf32(0.5f * l0);
        float tv1 = tanhf32(0.5f * l1);
        float tv2 = tanhf32(0.5f * l2);
        float tv3 = tanhf32(0.5f * l3);
        float tv4 = tanhf32(0.5f * l4);
        float tv5 = tanhf32(0.5f * l5);
        float tv6 = tanhf32(0.5f * l6);

        float t0h = 0.5f * tv0, t1h = 0.5f * tv1, t3h = 0.5f * tv3;
        float pb0 = tv4 * tv6, pa0 = t0h * tv2;
        m01 = t0h * pb0;  m02 = pa0 * tv6;  m03 = pa0 * tv4;
        float pb1 = tv5 * tv6, pa1 = t1h * tv2;
        m11 = t1h * pb1;  m12 = pa1 * tv6;  m13 = pa1 * tv5;
        float pb2 = tv5 * tv6, pa2 = t3h * tv4;
        m21 = t3h * pb2;  m22 = pa2 * tv6;  m23 = pa2 * tv5;

        T2 = base2 + (m01 + m11);
        T4 = base4 + (m02 + m21);
        T5 = base5 + (m12 + m22);
        T6 = base6 + ((m03 + m13) + m23);
    }

    // ---------- iterations 2..4 ----------
#pragma unroll
    for (int it = 0; it < 3; ++it) {
        float t01 = tanhf32(T2 - m01), t02 = tanhf32(T4 - m02), t03 = tanhf32(T6 - m03);
        float t11 = tanhf32(T2 - m11), t12 = tanhf32(T5 - m12), t13 = tanhf32(T6 - m13);
        float t21 = tanhf32(T4 - m21), t22 = tanhf32(T5 - m22), t23 = tanhf32(T6 - m23);

        float pb0 = t02 * t03, pa0 = c0h * t01;
        m01 = c0h * pb0;  m02 = pa0 * t03;  m03 = pa0 * t02;
        float pb1 = t12 * t13, pa1 = c1h * t11;
        m11 = c1h * pb1;  m12 = pa1 * t13;  m13 = pa1 * t12;
        float pb2 = t22 * t23, pa2 = c3h * t21;
        m21 = c3h * pb2;  m22 = pa2 * t23;  m23 = pa2 * t22;

        T2 = base2 + (m01 + m11);
        T4 = base4 + (m02 + m21);
        T5 = base5 + (m12 + m22);
        T6 = base6 + ((m03 + m13) + m23);
    }

    // ---------- iteration 5 (also deg-1 messages for outputs) ----------
    float m00, m10, m20;
    {
        float t01 = tanhf32(T2 - m01), t02 = tanhf32(T4 - m02), t03 = tanhf32(T6 - m03);
        float t11 = tanhf32(T2 - m11), t12 = tanhf32(T5 - m12), t13 = tanhf32(T6 - m13);
        float t21 = tanhf32(T4 - m21), t22 = tanhf32(T5 - m22), t23 = tanhf32(T6 - m23);

        float pb0 = t02 * t03, pa0 = c0h * t01;
        m01 = c0h * pb0;  m02 = pa0 * t03;  m03 = pa0 * t02;
        m00 = t01 * (0.5f * pb0);
        float pb1 = t12 * t13, pa1 = c1h * t11;
        m11 = c1h * pb1;  m12 = pa1 * t13;  m13 = pa1 * t12;
        m10 = t11 * (0.5f * pb1);
        float pb2 = t22 * t23, pa2 = c3h * t21;
        m21 = c3h * pb2;  m22 = pa2 * t23;  m23 = pa2 * t22;
        m20 = t21 * (0.5f * pb2);

        T2 = base2 + (m01 + m11);
        T4 = base4 + (m02 + m21);
        T5 = base5 + (m12 + m22);
        T6 = base6 + ((m03 + m13) + m23);
    }

    __syncthreads();   // reuse s for outputs

    float* q = s + tid * 7;
    q[0] = 4.0f * ((l0 + 1.0f) + m00);
    q[1] = 4.0f * ((l1 + 1.0f) + m10);
    q[2] = 4.0f * T2;
    q[3] = 4.0f * ((l3 + 1.0f) + m20);
    q[4] = 4.0f * T4;
    q[5] = 4.0f * T5;
    q[6] = 4.0f * T6;

    __syncthreads();

    // ---- coalesced bulk store ----
    {
        float4* dst = out4 + (size_t)blockIdx.x * VEC4_PER_BLK;
        const float4* s4 = reinterpret_cast<const float4*>(s);
#pragma unroll
        for (int i = tid; i < VEC4_PER_BLK; i += TPB)
            dst[i] = s4[i];
    }
}

extern "C" void kernel_launch(void* const* d_in, const int* in_sizes, int n_in,
                              void* d_out, int out_size) {
    const float4* llr4 = (const float4*)d_in[0];
    float4* out4 = (float4*)d_out;
    int B = in_sizes[0] / 7;          // 262144, divisible by 256
    int blocks = B / TPB;             // 1024
    ldpc_bp_kernel<<<blocks, TPB>>>(llr4, out4);
}